// round 11
// baseline (speedup 1.0000x reference)
#include <cuda_runtime.h>
#include <cuda_fp16.h>
#include <cstdint>

#define E_TOT   30000
#define NB      10
#define WNUM    9216
#define EB      64
#define NTHR    128
#define INV_S3  0.5773502691896258f
#define PW0     0.10206207261596575f
#define PW1     0.17677669529663687f
#define PW1S    (PW1 * INV_S3)

#define NCH 102

// Packed half2 B fragments (u32 each), fragment-ordered per chunk (same as R10).
__device__ uint32_t g_B1[51 * 1024];   // N=64 chunks: c<34 Wa halves, c>=34 Wd
__device__ uint32_t g_B2[34 * 512];    // N=32 chunks: Wb halves
__device__ uint32_t g_B3[17 * 512];    // N=32 chunks: Wc

// SMEM float offsets (13792 floats = 53.9 KB -> 4 CTAs/SM)
#define OFF_H    0        // [17][64]  = 1088
#define OFF_X0   1088     // [64][65]  = 4160 (later: zAd rows 0-31, pb stash above)
#define OFF_ZAD  OFF_X0               // [32][65] = 2080
#define OFF_PB   (OFF_X0 + 2080)      // [32][65] = 2080
#define OFF_XC   5248     // [96][65]  = 6240
#define OFF_SH0  11488    // [64]
#define OFF_SH1  11552    // [3][64]
#define OFF_BB   11744    // 2 x 1024 u32 staging
#define SMEM_FL  13792
#define SMEM_BYTES (SMEM_FL * 4)

__device__ __forceinline__ uint32_t pkh2(float lo, float hi) {
    __half2 h = __floats2half2_rn(lo, hi);
    return *reinterpret_cast<uint32_t*>(&h);
}
__device__ __forceinline__ uint32_t smem_u32(const void* p) {
    uint32_t a;
    asm("{ .reg .u64 t; cvta.to.shared.u64 t, %1; cvt.u32.u64 %0, t; }" : "=r"(a) : "l"(p));
    return a;
}
__device__ __forceinline__ void cpa16(uint32_t s, const void* g) {
    asm volatile("cp.async.cg.shared.global [%0], [%1], 16;" :: "r"(s), "l"(g));
}
#define CP_COMMIT() asm volatile("cp.async.commit_group;")
#define CP_WAIT0()  asm volatile("cp.async.wait_group 0;")

__device__ __forceinline__ void mma16(float (&d)[4], const uint32_t (&a)[4],
                                      uint32_t b0, uint32_t b1) {
    asm volatile(
        "mma.sync.aligned.m16n8k16.row.col.f32.f16.f16.f32 "
        "{%0,%1,%2,%3}, {%4,%5,%6,%7}, {%8,%9}, {%0,%1,%2,%3};"
        : "+f"(d[0]), "+f"(d[1]), "+f"(d[2]), "+f"(d[3])
        : "r"(a[0]), "r"(a[1]), "r"(a[2]), "r"(a[3]), "r"(b0), "r"(b1));
}

// ---------------------------------------------------------------------------
// Prep: gather w2/b2 into fp16 fragment-ordered chunks (identical to R10).
// ---------------------------------------------------------------------------
__global__ void prep_kernel(const float* __restrict__ w2, const float* __restrict__ b2) {
    int i = blockIdx.x * 256 + threadIdx.x;
    if (i < 51 * 1024) {                       // B1 (NT=8, N=64)
        int c = i >> 10, w = i & 1023;
        int p = w & 1, lane = (w >> 1) & 31, q = w >> 6;
        int s = q >> 3, nt = q & 7;
        int j = c / 17, k = c % 17;
        int kk = s * 16 + (lane & 3) * 2 + p * 8;
        int n  = nt * 8 + (lane >> 2);
        int col0 = (j < 2) ? ((j * 32 + kk) * 64 + n)     : (7168 + kk * 64 + n);
        int col1 = (j < 2) ? ((j * 32 + kk + 1) * 64 + n) : (7168 + (kk + 1) * 64 + n);
        float v0 = (k < 16) ? w2[k * WNUM + col0] : b2[col0];
        float v1 = (k < 16) ? w2[k * WNUM + col1] : b2[col1];
        g_B1[i] = pkh2(v0, v1);
        return;
    }
    i -= 51 * 1024;
    if (i < 34 * 512) {                        // B2 (NT=4, N=32)
        int c = i >> 9, w = i & 511;
        int p = w & 1, lane = (w >> 1) & 31, q = w >> 6;
        int s = q >> 2, nt = q & 3;
        int j = c / 17, k = c % 17;
        int kk = s * 16 + (lane & 3) * 2 + p * 8;
        int n  = nt * 8 + (lane >> 2);
        int col0 = 4096 + (j * 32 + kk) * 32 + n;
        int col1 = 4096 + (j * 32 + kk + 1) * 32 + n;
        float v0 = (k < 16) ? w2[k * WNUM + col0] : b2[col0];
        float v1 = (k < 16) ? w2[k * WNUM + col1] : b2[col1];
        g_B2[c * 512 + w] = pkh2(v0, v1);
        return;
    }
    i -= 34 * 512;
    if (i < 17 * 512) {                        // B3 (NT=4, N=32)
        int c = i >> 9, w = i & 511;
        int p = w & 1, lane = (w >> 1) & 31, q = w >> 6;
        int s = q >> 2, nt = q & 3;
        int k = c;
        int kk = s * 16 + (lane & 3) * 2 + p * 8;
        int n  = nt * 8 + (lane >> 2);
        int col0 = 6144 + kk * 32 + n;
        int col1 = 6144 + (kk + 1) * 32 + n;
        float v0 = (k < 16) ? w2[k * WNUM + col0] : b2[col0];
        float v1 = (k < 16) ? w2[k * WNUM + col1] : b2[col1];
        g_B3[c * 512 + w] = pkh2(v0, v1);
    }
}

// Chunk order: [0,34) Wa | [34,68) Wb | [68,85) Wd | [85,102) Wc
__device__ __forceinline__ const uint32_t* chunk_src(int c, int& nu) {
    if (c < 34) { nu = 1024; return g_B1 + c * 1024; }
    if (c < 68) { nu = 512;  return g_B2 + (c - 34) * 512; }
    if (c < 85) { nu = 1024; return g_B1 + (c - 34) * 1024; }
    nu = 512; return g_B3 + (c - 85) * 512;
}

__device__ __forceinline__ void stage_chunk(int c, uint32_t sbB, int t) {
    if (c < NCH) {
        int nu; const uint32_t* src = chunk_src(c, nu);
        uint32_t dst = sbB + (uint32_t)((c & 1) * 1024) * 4u;
        int units = nu / 4;
        for (int u = t; u < units; u += NTHR)
            cpa16(dst + (uint32_t)u * 16u, src + u * 4);
    }
    CP_COMMIT();
}

template<int NT>
__device__ __forceinline__ void run_seg(
    int cbase, const float* __restrict__ hb, float s00, float s01,
    const float* __restrict__ fb,
    float (&acc)[NT][4],
    int eb, int lane, int t,
    const float* __restrict__ smemf, uint32_t sbB)
{
    const int r0 = lane >> 2;
    const int vb = (lane & 3) * 2;
    float Ff[2][4][2];
    #pragma unroll
    for (int s = 0; s < 2; s++) {
        int v0 = s * 16 + vb;
        Ff[s][0][0] = fb[(v0 + 0) * 65 + eb + r0];
        Ff[s][0][1] = fb[(v0 + 0) * 65 + eb + r0 + 8];
        Ff[s][1][0] = fb[(v0 + 1) * 65 + eb + r0];
        Ff[s][1][1] = fb[(v0 + 1) * 65 + eb + r0 + 8];
        Ff[s][2][0] = fb[(v0 + 8) * 65 + eb + r0];
        Ff[s][2][1] = fb[(v0 + 8) * 65 + eb + r0 + 8];
        Ff[s][3][0] = fb[(v0 + 9) * 65 + eb + r0];
        Ff[s][3][1] = fb[(v0 + 9) * 65 + eb + r0 + 8];
    }
    for (int k = 0; k < 17; k++) {
        int c = cbase + k;
        CP_WAIT0();
        __syncthreads();
        stage_chunk(c + 1, sbB, t);
        const uint2* Bb = (const uint2*)(smemf + OFF_BB + (c & 1) * 1024);
        float h0 = hb[k * 64 + eb + r0] * s00;
        float h1 = hb[k * 64 + eb + r0 + 8] * s01;
        #pragma unroll
        for (int s = 0; s < 2; s++) {
            uint32_t a[4];
            a[0] = pkh2(h0 * Ff[s][0][0], h0 * Ff[s][1][0]);
            a[1] = pkh2(h1 * Ff[s][0][1], h1 * Ff[s][1][1]);
            a[2] = pkh2(h0 * Ff[s][2][0], h0 * Ff[s][3][0]);
            a[3] = pkh2(h1 * Ff[s][2][1], h1 * Ff[s][3][1]);
            #pragma unroll
            for (int nt = 0; nt < NT; nt++) {
                uint2 bv = Bb[(s * NT + nt) * 32 + lane];
                mma16(acc[nt], a, bv.x, bv.y);
            }
        }
    }
}

__device__ __forceinline__ void run_seg3(
    int cbase, const float* __restrict__ hb,
    const float* __restrict__ xcb,
    float (&pc)[3][4][4],
    int eb, int lane, int t,
    const float* __restrict__ smemf, uint32_t sbB)
{
    const int r0 = lane >> 2;
    const int vb = (lane & 3) * 2;
    float Ff[3][2][4][2];
    #pragma unroll
    for (int m = 0; m < 3; m++) {
        const float* fb = xcb + m * 65;
        #pragma unroll
        for (int s = 0; s < 2; s++) {
            int v0 = s * 16 + vb;
            Ff[m][s][0][0] = fb[(v0 + 0) * 195 + eb + r0];
            Ff[m][s][0][1] = fb[(v0 + 0) * 195 + eb + r0 + 8];
            Ff[m][s][1][0] = fb[(v0 + 1) * 195 + eb + r0];
            Ff[m][s][1][1] = fb[(v0 + 1) * 195 + eb + r0 + 8];
            Ff[m][s][2][0] = fb[(v0 + 8) * 195 + eb + r0];
            Ff[m][s][2][1] = fb[(v0 + 8) * 195 + eb + r0 + 8];
            Ff[m][s][3][0] = fb[(v0 + 9) * 195 + eb + r0];
            Ff[m][s][3][1] = fb[(v0 + 9) * 195 + eb + r0 + 8];
        }
    }
    for (int k = 0; k < 17; k++) {
        int c = cbase + k;
        CP_WAIT0();
        __syncthreads();
        stage_chunk(c + 1, sbB, t);
        const uint2* Bb = (const uint2*)(smemf + OFF_BB + (c & 1) * 1024);
        float h0 = hb[k * 64 + eb + r0];
        float h1 = hb[k * 64 + eb + r0 + 8];
        #pragma unroll
        for (int s = 0; s < 2; s++) {
            uint32_t a[3][4];
            #pragma unroll
            for (int m = 0; m < 3; m++) {
                a[m][0] = pkh2(h0 * Ff[m][s][0][0], h0 * Ff[m][s][1][0]);
                a[m][1] = pkh2(h1 * Ff[m][s][0][1], h1 * Ff[m][s][1][1]);
                a[m][2] = pkh2(h0 * Ff[m][s][2][0], h0 * Ff[m][s][3][0]);
                a[m][3] = pkh2(h1 * Ff[m][s][2][1], h1 * Ff[m][s][3][1]);
            }
            #pragma unroll
            for (int nt = 0; nt < 4; nt++) {
                uint2 bv = Bb[(s * 4 + nt) * 32 + lane];
                #pragma unroll
                for (int m = 0; m < 3; m++)
                    mma16(pc[m][nt], a[m], bv.x, bv.y);
            }
        }
    }
}

extern __shared__ float smem[];

__global__ void __launch_bounds__(NTHR, 4) conv_mma_kernel(
    const float* __restrict__ x,    const float* __restrict__ rps,
    const float* __restrict__ dist, const float* __restrict__ freq,
    const float* __restrict__ w1,   const float* __restrict__ b1,
    float* __restrict__ out)
{
    const int t    = threadIdx.x;
    const int wid  = t >> 5;
    const int lane = t & 31;
    const int eb   = wid * 16;          // 4 warps x 16 edges
    const int e0   = blockIdx.x * EB;
    const uint32_t sbB = smem_u32(smem) + OFF_BB * 4;

    // prologue prefetch (overlaps setup)
    stage_chunk(0, sbB, t);

    // --- setup: radial MLP + sh (threads 0..63) ---
    if (t < EB) {
        int e = e0 + t;
        if (e < E_TOT) {
            float d  = dist[e] * 0.25f;
            float id = 1.0f / d;
            float d2 = d * d;
            float d5 = d2 * d2 * d;
            float env = id - 28.0f * d5 + 48.0f * d5 * d - 21.0f * d5 * d2;
            env = (d < 1.0f) ? env : 0.0f;
            float basis[NB];
            #pragma unroll
            for (int i = 0; i < NB; i++) basis[i] = env * sinf(freq[i] * d);
            float s0 = rps[e * 4 + 0];
            smem[OFF_SH0 + t]          = s0;
            smem[OFF_SH1 + 0 * 64 + t] = rps[e * 4 + 1];
            smem[OFF_SH1 + 1 * 64 + t] = rps[e * 4 + 2];
            smem[OFF_SH1 + 2 * 64 + t] = rps[e * 4 + 3];
            #pragma unroll
            for (int k = 0; k < 16; k++) {
                float pre = b1[k];
                #pragma unroll
                for (int i = 0; i < NB; i++) pre = fmaf(basis[i], w1[i * 16 + k], pre);
                float sg = 1.0f / (1.0f + expf(-pre));
                smem[OFF_H + k * 64 + t] = pre * sg;
            }
            smem[OFF_H + 16 * 64 + t] = 1.0f;
        } else {
            #pragma unroll
            for (int k = 0; k < 17; k++) smem[OFF_H + k * 64 + t] = 0.0f;
            smem[OFF_SH0 + t] = 0.0f;
            smem[OFF_SH1 + 0 * 64 + t] = 0.0f;
            smem[OFF_SH1 + 1 * 64 + t] = 0.0f;
            smem[OFF_SH1 + 2 * 64 + t] = 0.0f;
        }
    }

    // --- x tiles (transposed, stride 65) ---
    for (int idx = t; idx < EB * 40; idx += NTHR) {
        int el = idx / 40, c4 = idx - el * 40;
        int e  = e0 + el;
        float4 v = make_float4(0.f, 0.f, 0.f, 0.f);
        if (e < E_TOT) v = *(const float4*)&x[(size_t)e * 160 + c4 * 4];
        if (c4 < 16) {
            int vb = c4 * 4;
            smem[OFF_X0 + (vb + 0) * 65 + el] = v.x;
            smem[OFF_X0 + (vb + 1) * 65 + el] = v.y;
            smem[OFF_X0 + (vb + 2) * 65 + el] = v.z;
            smem[OFF_X0 + (vb + 3) * 65 + el] = v.w;
        } else {
            int vb = c4 * 4 - 64;
            smem[OFF_XC + (vb + 0) * 65 + el] = v.x;
            smem[OFF_XC + (vb + 1) * 65 + el] = v.y;
            smem[OFF_XC + (vb + 2) * 65 + el] = v.z;
            smem[OFF_XC + (vb + 3) * 65 + el] = v.w;
        }
    }
    __syncthreads();

    const float* H = smem + OFF_H;
    const float s00 = smem[OFF_SH0 + eb + (lane >> 2)];
    const float s01 = smem[OFF_SH0 + eb + (lane >> 2) + 8];

    // --- phase 1a/1b: Wa on x0 (A = h*sh0*x0) ---
    float acc1[8][4];
    #pragma unroll
    for (int i = 0; i < 8; i++) { acc1[i][0]=acc1[i][1]=acc1[i][2]=acc1[i][3]=0.f; }
    run_seg<8>(0,  H, s00, s01, smem + OFF_X0,           acc1, eb, lane, t, smem, sbB);
    run_seg<8>(17, H, s00, s01, smem + OFF_X0 + 32 * 65, acc1, eb, lane, t, smem, sbB);

    // --- phase 2: Wb on x0 (A = h*x0) -> pb ---
    float acc2[4][4];
    #pragma unroll
    for (int i = 0; i < 4; i++) { acc2[i][0]=acc2[i][1]=acc2[i][2]=acc2[i][3]=0.f; }
    run_seg<4>(34, H, 1.0f, 1.0f, smem + OFF_X0,           acc2, eb, lane, t, smem, sbB);
    run_seg<4>(51, H, 1.0f, 1.0f, smem + OFF_X0 + 32 * 65, acc2, eb, lane, t, smem, sbB);

    // --- X0 dead: stash pb, build zAd ---
    __syncthreads();
    {
        const int r0 = lane >> 2, cpair = 2 * (lane & 3);
        float* pbS = smem + OFF_PB;
        #pragma unroll
        for (int nt = 0; nt < 4; nt++) {
            int w0 = nt * 8 + cpair;
            pbS[(w0 + 0) * 65 + eb + r0]     = acc2[nt][0];
            pbS[(w0 + 1) * 65 + eb + r0]     = acc2[nt][1];
            pbS[(w0 + 0) * 65 + eb + r0 + 8] = acc2[nt][2];
            pbS[(w0 + 1) * 65 + eb + r0 + 8] = acc2[nt][3];
        }
    }
    for (int idx = t; idx < 32 * 64; idx += NTHR) {
        int u = idx >> 6, el = idx & 63;
        float a = smem[OFF_XC + (u * 3 + 0) * 65 + el] * smem[OFF_SH1 + 0 * 64 + el]
                + smem[OFF_XC + (u * 3 + 1) * 65 + el] * smem[OFF_SH1 + 1 * 64 + el]
                + smem[OFF_XC + (u * 3 + 2) * 65 + el] * smem[OFF_SH1 + 2 * 64 + el];
        smem[OFF_ZAD + u * 65 + el] = INV_S3 * a;
    }
    __syncthreads();

    // --- phase 1c: Wd on zAd ---
    run_seg<8>(68, H, 1.0f, 1.0f, smem + OFF_ZAD, acc1, eb, lane, t, smem, sbB);

    // out0 epilogue
    const int r0 = lane >> 2, cpair = 2 * (lane & 3);
    #pragma unroll
    for (int nt = 0; nt < 8; nt++) {
        int col = nt * 8 + cpair;
        int eA = e0 + eb + r0;
        if (eA < E_TOT)
            *(float2*)&out[(size_t)eA * 160 + col] =
                make_float2(PW0 * acc1[nt][0], PW0 * acc1[nt][1]);
        int eB = eA + 8;
        if (eB < E_TOT)
            *(float2*)&out[(size_t)eB * 160 + col] =
                make_float2(PW0 * acc1[nt][2], PW0 * acc1[nt][3]);
    }

    // --- phase 3: Wc on xc -> pc ---
    float pcx[3][4][4];
    #pragma unroll
    for (int m = 0; m < 3; m++)
        #pragma unroll
        for (int i = 0; i < 4; i++) { pcx[m][i][0]=pcx[m][i][1]=pcx[m][i][2]=pcx[m][i][3]=0.f; }
    run_seg3(85, H, smem + OFF_XC, pcx, eb, lane, t, smem, sbB);

    // --- out1 epilogue ---
    const float* pbS = smem + OFF_PB;
    #pragma unroll
    for (int nt = 0; nt < 4; nt++) {
        int w0 = nt * 8 + cpair;
        #pragma unroll
        for (int half = 0; half < 2; half++) {
            int el = eb + r0 + half * 8;
            int e  = e0 + el;
            if (e >= E_TOT) continue;
            float s0v = smem[OFF_SH0 + el];
            float s1v[3];
            #pragma unroll
            for (int m = 0; m < 3; m++) s1v[m] = smem[OFF_SH1 + m * 64 + el];
            float pb0 = pbS[(w0 + 0) * 65 + el];
            float pb1 = pbS[(w0 + 1) * 65 + el];
            float vals[6];
            #pragma unroll
            for (int m = 0; m < 3; m++) {
                vals[m]     = PW1S * (pb0 * s1v[m] + pcx[m][nt][half * 2 + 0] * s0v);
                vals[3 + m] = PW1S * (pb1 * s1v[m] + pcx[m][nt][half * 2 + 1] * s0v);
            }
            size_t base = (size_t)e * 160 + 64 + 3 * w0;
            *(float2*)&out[base + 0] = make_float2(vals[0], vals[1]);
            *(float2*)&out[base + 2] = make_float2(vals[2], vals[3]);
            *(float2*)&out[base + 4] = make_float2(vals[4], vals[5]);
        }
    }
}

extern "C" void kernel_launch(void* const* d_in, const int* in_sizes, int n_in,
                              void* d_out, int out_size) {
    (void)in_sizes; (void)n_in; (void)out_size;
    const float* x    = (const float*)d_in[0];
    const float* rps  = (const float*)d_in[1];
    const float* dist = (const float*)d_in[2];
    const float* freq = (const float*)d_in[3];
    const float* w1   = (const float*)d_in[4];
    const float* b1   = (const float*)d_in[5];
    const float* w2   = (const float*)d_in[6];
    const float* b2   = (const float*)d_in[7];
    float* out = (float*)d_out;

    const int tot = 51 * 1024 + 34 * 512 + 17 * 512;
    prep_kernel<<<(tot + 255) / 256, 256>>>(w2, b2);

    cudaFuncSetAttribute(conv_mma_kernel,
                         cudaFuncAttributeMaxDynamicSharedMemorySize, SMEM_BYTES);
    const int nblocks = (E_TOT + EB - 1) / EB;   // 469
    conv_mma_kernel<<<nblocks, NTHR, SMEM_BYTES>>>(x, rps, dist, freq, w1, b1, out);
}

// round 12
// speedup vs baseline: 1.5488x; 1.5488x over previous
#include <cuda_runtime.h>
#include <cuda_fp16.h>
#include <cstdint>

#define E_TOT   30000
#define NB      10
#define WNUM    9216
#define EB      128
#define NTHR    256
#define INV_S3  0.5773502691896258f
#define PW0     0.10206207261596575f
#define PW1     0.17677669529663687f
#define PW1S    (PW1 * INV_S3)

#define NCH 102

// Packed half2 B fragments (u32 each), fragment-ordered per chunk (same as R10).
__device__ uint32_t g_B1[51 * 1024];   // N=64 chunks: c<34 Wa halves, c>=34 Wd
__device__ uint32_t g_B2[34 * 512];    // N=32 chunks: Wb halves
__device__ uint32_t g_B3[17 * 512];    // N=32 chunks: Wc

// SMEM float offsets (27424 floats = 107.1 KB -> 2 CTAs/SM)
#define OFF_H    0        // [17][128]
#define OFF_X0   2176     // [64][129]  (later: zAd rows 0-31, pb stash above)
#define OFF_ZAD  OFF_X0
#define OFF_PB   (OFF_X0 + 4128)
#define OFF_XC   10432    // [96][129]
#define OFF_SH0  22816    // [128]
#define OFF_SH1  22944    // [3][128]
#define OFF_BB   23328    // 2 x 2048 u32 slot buffers (each holds a chunk PAIR)
#define SMEM_FL  27424
#define SMEM_BYTES (SMEM_FL * 4)

__device__ __forceinline__ uint32_t pkh2(float lo, float hi) {
    __half2 h = __floats2half2_rn(lo, hi);
    return *reinterpret_cast<uint32_t*>(&h);
}
__device__ __forceinline__ uint32_t smem_u32(const void* p) {
    uint32_t a;
    asm("{ .reg .u64 t; cvta.to.shared.u64 t, %1; cvt.u32.u64 %0, t; }" : "=r"(a) : "l"(p));
    return a;
}
__device__ __forceinline__ void cpa16(uint32_t s, const void* g) {
    asm volatile("cp.async.cg.shared.global [%0], [%1], 16;" :: "r"(s), "l"(g));
}
#define CP_COMMIT() asm volatile("cp.async.commit_group;")
#define CP_WAIT0()  asm volatile("cp.async.wait_group 0;")

__device__ __forceinline__ void mma16(float (&d)[4], const uint32_t (&a)[4],
                                      uint32_t b0, uint32_t b1) {
    asm volatile(
        "mma.sync.aligned.m16n8k16.row.col.f32.f16.f16.f32 "
        "{%0,%1,%2,%3}, {%4,%5,%6,%7}, {%8,%9}, {%0,%1,%2,%3};"
        : "+f"(d[0]), "+f"(d[1]), "+f"(d[2]), "+f"(d[3])
        : "r"(a[0]), "r"(a[1]), "r"(a[2]), "r"(a[3]), "r"(b0), "r"(b1));
}

// ---------------------------------------------------------------------------
// Prep: gather w2/b2 into fp16 fragment-ordered chunks (identical to R10).
// ---------------------------------------------------------------------------
__global__ void prep_kernel(const float* __restrict__ w2, const float* __restrict__ b2) {
    int i = blockIdx.x * 256 + threadIdx.x;
    if (i < 51 * 1024) {                       // B1 (NT=8, N=64)
        int c = i >> 10, w = i & 1023;
        int p = w & 1, lane = (w >> 1) & 31, q = w >> 6;
        int s = q >> 3, nt = q & 7;
        int j = c / 17, k = c % 17;
        int kk = s * 16 + (lane & 3) * 2 + p * 8;
        int n  = nt * 8 + (lane >> 2);
        int col0 = (j < 2) ? ((j * 32 + kk) * 64 + n)     : (7168 + kk * 64 + n);
        int col1 = (j < 2) ? ((j * 32 + kk + 1) * 64 + n) : (7168 + (kk + 1) * 64 + n);
        float v0 = (k < 16) ? w2[k * WNUM + col0] : b2[col0];
        float v1 = (k < 16) ? w2[k * WNUM + col1] : b2[col1];
        g_B1[i] = pkh2(v0, v1);
        return;
    }
    i -= 51 * 1024;
    if (i < 34 * 512) {                        // B2 (NT=4, N=32)
        int c = i >> 9, w = i & 511;
        int p = w & 1, lane = (w >> 1) & 31, q = w >> 6;
        int s = q >> 2, nt = q & 3;
        int j = c / 17, k = c % 17;
        int kk = s * 16 + (lane & 3) * 2 + p * 8;
        int n  = nt * 8 + (lane >> 2);
        int col0 = 4096 + (j * 32 + kk) * 32 + n;
        int col1 = 4096 + (j * 32 + kk + 1) * 32 + n;
        float v0 = (k < 16) ? w2[k * WNUM + col0] : b2[col0];
        float v1 = (k < 16) ? w2[k * WNUM + col1] : b2[col1];
        g_B2[c * 512 + w] = pkh2(v0, v1);
        return;
    }
    i -= 34 * 512;
    if (i < 17 * 512) {                        // B3 (NT=4, N=32)
        int c = i >> 9, w = i & 511;
        int p = w & 1, lane = (w >> 1) & 31, q = w >> 6;
        int s = q >> 2, nt = q & 3;
        int k = c;
        int kk = s * 16 + (lane & 3) * 2 + p * 8;
        int n  = nt * 8 + (lane >> 2);
        int col0 = 6144 + kk * 32 + n;
        int col1 = 6144 + (kk + 1) * 32 + n;
        float v0 = (k < 16) ? w2[k * WNUM + col0] : b2[col0];
        float v1 = (k < 16) ? w2[k * WNUM + col1] : b2[col1];
        g_B3[c * 512 + w] = pkh2(v0, v1);
    }
}

// Chunk order: [0,34) Wa | [34,68) Wb | [68,85) Wd | [85,102) Wc
__device__ __forceinline__ const uint32_t* chunk_src(int c, int& nu) {
    if (c < 34) { nu = 1024; return g_B1 + c * 1024; }
    if (c < 68) { nu = 512;  return g_B2 + (c - 34) * 512; }
    if (c < 85) { nu = 1024; return g_B1 + (c - 34) * 1024; }
    nu = 512; return g_B3 + (c - 85) * 512;
}

// Stage `cnt` consecutive chunks (one slot) into buffer `buf` (2048 u32).
__device__ __forceinline__ void stage_slot(int c0, int cnt, int buf,
                                           uint32_t sbB, int t) {
    uint32_t dst = sbB + (uint32_t)buf * 8192u;   // 2048 u32 = 8192 B
    int off = 0;
    for (int i = 0; i < cnt; i++) {
        int c = c0 + i;
        if (c >= NCH) break;
        int nu; const uint32_t* src = chunk_src(c, nu);
        int units = nu / 4;
        if (t < units) cpa16(dst + (uint32_t)(off + t * 4) * 4u, src + t * 4);
        off += nu;
    }
    CP_COMMIT();
}

// Process one 17-chunk segment as 8 pairs + 1 single; slot0 = global slot index
// of this segment's first slot; next_c0 = first chunk of the NEXT segment.
template<int NT>
__device__ __forceinline__ void run_seg(
    int cbase, const float* __restrict__ hb, float s00, float s01,
    const float* __restrict__ fb,
    float (&acc)[NT][4],
    int eb, int lane, int t,
    const float* __restrict__ smemf, uint32_t sbB,
    int slot0, int next_c0)
{
    const int r0 = lane >> 2;
    const int vb = (lane & 3) * 2;
    const int NU = NT * 128;          // u32 per chunk
    float Ff[2][4][2];
    #pragma unroll
    for (int s = 0; s < 2; s++) {
        int v0 = s * 16 + vb;
        Ff[s][0][0] = fb[(v0 + 0) * 129 + eb + r0];
        Ff[s][0][1] = fb[(v0 + 0) * 129 + eb + r0 + 8];
        Ff[s][1][0] = fb[(v0 + 1) * 129 + eb + r0];
        Ff[s][1][1] = fb[(v0 + 1) * 129 + eb + r0 + 8];
        Ff[s][2][0] = fb[(v0 + 8) * 129 + eb + r0];
        Ff[s][2][1] = fb[(v0 + 8) * 129 + eb + r0 + 8];
        Ff[s][3][0] = fb[(v0 + 9) * 129 + eb + r0];
        Ff[s][3][1] = fb[(v0 + 9) * 129 + eb + r0 + 8];
    }
    auto do_chunk = [&](int k, const uint2* __restrict__ Bb) {
        float h0 = hb[k * 128 + eb + r0] * s00;
        float h1 = hb[k * 128 + eb + r0 + 8] * s01;
        #pragma unroll
        for (int s = 0; s < 2; s++) {
            uint32_t a[4];
            a[0] = pkh2(h0 * Ff[s][0][0], h0 * Ff[s][1][0]);
            a[1] = pkh2(h1 * Ff[s][0][1], h1 * Ff[s][1][1]);
            a[2] = pkh2(h0 * Ff[s][2][0], h0 * Ff[s][3][0]);
            a[3] = pkh2(h1 * Ff[s][2][1], h1 * Ff[s][3][1]);
            #pragma unroll
            for (int nt = 0; nt < NT; nt++) {
                uint2 bv = Bb[(s * NT + nt) * 32 + lane];
                mma16(acc[nt], a, bv.x, bv.y);
            }
        }
    };
    for (int p = 0; p < 8; p++) {
        int c = cbase + 2 * p;
        CP_WAIT0();
        __syncthreads();
        if (p < 7) stage_slot(c + 2, 2, (slot0 + p + 1) & 1, sbB, t);
        else       stage_slot(c + 2, 1, (slot0 + 8) & 1, sbB, t);
        const float* bbase = smemf + OFF_BB + (size_t)(((slot0 + p) & 1) * 2048);
        do_chunk(2 * p,     (const uint2*)bbase);
        do_chunk(2 * p + 1, (const uint2*)(bbase + NU));
    }
    // single slot: k = 16
    CP_WAIT0();
    __syncthreads();
    stage_slot(next_c0, 2, (slot0 + 9) & 1, sbB, t);
    do_chunk(16, (const uint2*)(smemf + OFF_BB + (size_t)(((slot0 + 8) & 1) * 2048)));
}

__device__ __forceinline__ void run_seg3(
    int cbase, const float* __restrict__ hb,
    const float* __restrict__ xcb,
    float (&pc)[3][4][4],
    int eb, int lane, int t,
    const float* __restrict__ smemf, uint32_t sbB,
    int slot0)
{
    const int r0 = lane >> 2;
    const int vb = (lane & 3) * 2;
    float Ff[3][2][4][2];
    #pragma unroll
    for (int m = 0; m < 3; m++) {
        const float* fb = xcb + m * 129;
        #pragma unroll
        for (int s = 0; s < 2; s++) {
            int v0 = s * 16 + vb;
            Ff[m][s][0][0] = fb[(v0 + 0) * 387 + eb + r0];
            Ff[m][s][0][1] = fb[(v0 + 0) * 387 + eb + r0 + 8];
            Ff[m][s][1][0] = fb[(v0 + 1) * 387 + eb + r0];
            Ff[m][s][1][1] = fb[(v0 + 1) * 387 + eb + r0 + 8];
            Ff[m][s][2][0] = fb[(v0 + 8) * 387 + eb + r0];
            Ff[m][s][2][1] = fb[(v0 + 8) * 387 + eb + r0 + 8];
            Ff[m][s][3][0] = fb[(v0 + 9) * 387 + eb + r0];
            Ff[m][s][3][1] = fb[(v0 + 9) * 387 + eb + r0 + 8];
        }
    }
    auto do_chunk = [&](int k, const uint2* __restrict__ Bb) {
        float h0 = hb[k * 128 + eb + r0];
        float h1 = hb[k * 128 + eb + r0 + 8];
        #pragma unroll
        for (int s = 0; s < 2; s++) {
            uint32_t a[3][4];
            #pragma unroll
            for (int m = 0; m < 3; m++) {
                a[m][0] = pkh2(h0 * Ff[m][s][0][0], h0 * Ff[m][s][1][0]);
                a[m][1] = pkh2(h1 * Ff[m][s][0][1], h1 * Ff[m][s][1][1]);
                a[m][2] = pkh2(h0 * Ff[m][s][2][0], h0 * Ff[m][s][3][0]);
                a[m][3] = pkh2(h1 * Ff[m][s][2][1], h1 * Ff[m][s][3][1]);
            }
            #pragma unroll
            for (int nt = 0; nt < 4; nt++) {
                uint2 bv = Bb[(s * 4 + nt) * 32 + lane];
                #pragma unroll
                for (int m = 0; m < 3; m++)
                    mma16(pc[m][nt], a[m], bv.x, bv.y);
            }
        }
    };
    for (int p = 0; p < 8; p++) {
        int c = cbase + 2 * p;
        CP_WAIT0();
        __syncthreads();
        if (p < 7) stage_slot(c + 2, 2, (slot0 + p + 1) & 1, sbB, t);
        else       stage_slot(c + 2, 1, (slot0 + 8) & 1, sbB, t);
        const float* bbase = smemf + OFF_BB + (size_t)(((slot0 + p) & 1) * 2048);
        do_chunk(2 * p,     (const uint2*)bbase);
        do_chunk(2 * p + 1, (const uint2*)(bbase + 512));
    }
    CP_WAIT0();
    __syncthreads();
    do_chunk(16, (const uint2*)(smemf + OFF_BB + (size_t)(((slot0 + 8) & 1) * 2048)));
}

extern __shared__ float smem[];

__global__ void __launch_bounds__(NTHR, 2) conv_mma_kernel(
    const float* __restrict__ x,    const float* __restrict__ rps,
    const float* __restrict__ dist, const float* __restrict__ freq,
    const float* __restrict__ w1,   const float* __restrict__ b1,
    float* __restrict__ out)
{
    const int t    = threadIdx.x;
    const int wid  = t >> 5;
    const int lane = t & 31;
    const int eb   = wid * 16;
    const int e0   = blockIdx.x * EB;
    const uint32_t sbB = smem_u32(smem) + OFF_BB * 4;

    // prologue: stage slot 0 (chunks 0,1) — overlaps setup
    stage_slot(0, 2, 0, sbB, t);

    // --- setup: radial MLP + sh ---
    if (t < EB) {
        int e = e0 + t;
        if (e < E_TOT) {
            float d  = dist[e] * 0.25f;
            float id = 1.0f / d;
            float d2 = d * d;
            float d5 = d2 * d2 * d;
            float env = id - 28.0f * d5 + 48.0f * d5 * d - 21.0f * d5 * d2;
            env = (d < 1.0f) ? env : 0.0f;
            float basis[NB];
            #pragma unroll
            for (int i = 0; i < NB; i++) basis[i] = env * sinf(freq[i] * d);
            float s0 = rps[e * 4 + 0];
            smem[OFF_SH0 + t]           = s0;
            smem[OFF_SH1 + 0 * 128 + t] = rps[e * 4 + 1];
            smem[OFF_SH1 + 1 * 128 + t] = rps[e * 4 + 2];
            smem[OFF_SH1 + 2 * 128 + t] = rps[e * 4 + 3];
            #pragma unroll
            for (int k = 0; k < 16; k++) {
                float pre = b1[k];
                #pragma unroll
                for (int i = 0; i < NB; i++) pre = fmaf(basis[i], w1[i * 16 + k], pre);
                float sg = 1.0f / (1.0f + expf(-pre));
                smem[OFF_H + k * 128 + t] = pre * sg;
            }
            smem[OFF_H + 16 * 128 + t] = 1.0f;
        } else {
            #pragma unroll
            for (int k = 0; k < 17; k++) smem[OFF_H + k * 128 + t] = 0.0f;
            smem[OFF_SH0 + t] = 0.0f;
            smem[OFF_SH1 + 0 * 128 + t] = 0.0f;
            smem[OFF_SH1 + 1 * 128 + t] = 0.0f;
            smem[OFF_SH1 + 2 * 128 + t] = 0.0f;
        }
    }

    // --- x tiles (transposed, stride 129) ---
    for (int idx = t; idx < EB * 40; idx += NTHR) {
        int el = idx / 40, c4 = idx - el * 40;
        int e  = e0 + el;
        float4 v = make_float4(0.f, 0.f, 0.f, 0.f);
        if (e < E_TOT) v = *(const float4*)&x[(size_t)e * 160 + c4 * 4];
        if (c4 < 16) {
            int vb = c4 * 4;
            smem[OFF_X0 + (vb + 0) * 129 + el] = v.x;
            smem[OFF_X0 + (vb + 1) * 129 + el] = v.y;
            smem[OFF_X0 + (vb + 2) * 129 + el] = v.z;
            smem[OFF_X0 + (vb + 3) * 129 + el] = v.w;
        } else {
            int vb = c4 * 4 - 64;
            smem[OFF_XC + (vb + 0) * 129 + el] = v.x;
            smem[OFF_XC + (vb + 1) * 129 + el] = v.y;
            smem[OFF_XC + (vb + 2) * 129 + el] = v.z;
            smem[OFF_XC + (vb + 3) * 129 + el] = v.w;
        }
    }
    __syncthreads();

    const float* H = smem + OFF_H;
    const float s00 = smem[OFF_SH0 + eb + (lane >> 2)];
    const float s01 = smem[OFF_SH0 + eb + (lane >> 2) + 8];

    // --- phase 1a/1b: Wa on x0 (A = h*sh0*x0) ---
    float acc1[8][4];
    #pragma unroll
    for (int i = 0; i < 8; i++) { acc1[i][0]=acc1[i][1]=acc1[i][2]=acc1[i][3]=0.f; }
    run_seg<8>(0,  H, s00, s01, smem + OFF_X0,            acc1, eb, lane, t, smem, sbB, 0,  17);
    run_seg<8>(17, H, s00, s01, smem + OFF_X0 + 32 * 129, acc1, eb, lane, t, smem, sbB, 9,  34);

    // --- phase 2: Wb on x0 (A = h*x0) -> pb ---
    float acc2[4][4];
    #pragma unroll
    for (int i = 0; i < 4; i++) { acc2[i][0]=acc2[i][1]=acc2[i][2]=acc2[i][3]=0.f; }
    run_seg<4>(34, H, 1.0f, 1.0f, smem + OFF_X0,            acc2, eb, lane, t, smem, sbB, 18, 51);
    run_seg<4>(51, H, 1.0f, 1.0f, smem + OFF_X0 + 32 * 129, acc2, eb, lane, t, smem, sbB, 27, 68);

    // --- X0 dead: stash pb, build zAd ---
    __syncthreads();
    {
        const int r0 = lane >> 2, cpair = 2 * (lane & 3);
        float* pbS = smem + OFF_PB;
        #pragma unroll
        for (int nt = 0; nt < 4; nt++) {
            int w0 = nt * 8 + cpair;
            pbS[(w0 + 0) * 129 + eb + r0]     = acc2[nt][0];
            pbS[(w0 + 1) * 129 + eb + r0]     = acc2[nt][1];
            pbS[(w0 + 0) * 129 + eb + r0 + 8] = acc2[nt][2];
            pbS[(w0 + 1) * 129 + eb + r0 + 8] = acc2[nt][3];
        }
    }
    for (int idx = t; idx < 32 * 128; idx += NTHR) {
        int u = idx >> 7, el = idx & 127;
        float a = smem[OFF_XC + (u * 3 + 0) * 129 + el] * smem[OFF_SH1 + 0 * 128 + el]
                + smem[OFF_XC + (u * 3 + 1) * 129 + el] * smem[OFF_SH1 + 1 * 128 + el]
                + smem[OFF_XC + (u * 3 + 2) * 129 + el] * smem[OFF_SH1 + 2 * 128 + el];
        smem[OFF_ZAD + u * 129 + el] = INV_S3 * a;
    }
    __syncthreads();

    // --- phase 1c: Wd on zAd ---
    run_seg<8>(68, H, 1.0f, 1.0f, smem + OFF_ZAD, acc1, eb, lane, t, smem, sbB, 36, 85);

    // out0 epilogue
    const int r0 = lane >> 2, cpair = 2 * (lane & 3);
    #pragma unroll
    for (int nt = 0; nt < 8; nt++) {
        int col = nt * 8 + cpair;
        int eA = e0 + eb + r0;
        if (eA < E_TOT)
            *(float2*)&out[(size_t)eA * 160 + col] =
                make_float2(PW0 * acc1[nt][0], PW0 * acc1[nt][1]);
        int eB = eA + 8;
        if (eB < E_TOT)
            *(float2*)&out[(size_t)eB * 160 + col] =
                make_float2(PW0 * acc1[nt][2], PW0 * acc1[nt][3]);
    }

    // --- phase 3: Wc on xc -> pc ---
    float pcx[3][4][4];
    #pragma unroll
    for (int m = 0; m < 3; m++)
        #pragma unroll
        for (int i = 0; i < 4; i++) { pcx[m][i][0]=pcx[m][i][1]=pcx[m][i][2]=pcx[m][i][3]=0.f; }
    run_seg3(85, H, smem + OFF_XC, pcx, eb, lane, t, smem, sbB, 45);

    // --- out1 epilogue ---
    const float* pbS = smem + OFF_PB;
    #pragma unroll
    for (int nt = 0; nt < 4; nt++) {
        int w0 = nt * 8 + cpair;
        #pragma unroll
        for (int half = 0; half < 2; half++) {
            int el = eb + r0 + half * 8;
            int e  = e0 + el;
            if (e >= E_TOT) continue;
            float s0v = smem[OFF_SH0 + el];
            float s1v[3];
            #pragma unroll
            for (int m = 0; m < 3; m++) s1v[m] = smem[OFF_SH1 + m * 128 + el];
            float pb0 = pbS[(w0 + 0) * 129 + el];
            float pb1 = pbS[(w0 + 1) * 129 + el];
            float vals[6];
            #pragma unroll
            for (int m = 0; m < 3; m++) {
                vals[m]     = PW1S * (pb0 * s1v[m] + pcx[m][nt][half * 2 + 0] * s0v);
                vals[3 + m] = PW1S * (pb1 * s1v[m] + pcx[m][nt][half * 2 + 1] * s0v);
            }
            size_t base = (size_t)e * 160 + 64 + 3 * w0;
            *(float2*)&out[base + 0] = make_float2(vals[0], vals[1]);
            *(float2*)&out[base + 2] = make_float2(vals[2], vals[3]);
            *(float2*)&out[base + 4] = make_float2(vals[4], vals[5]);
        }
    }
}

extern "C" void kernel_launch(void* const* d_in, const int* in_sizes, int n_in,
                              void* d_out, int out_size) {
    (void)in_sizes; (void)n_in; (void)out_size;
    const float* x    = (const float*)d_in[0];
    const float* rps  = (const float*)d_in[1];
    const float* dist = (const float*)d_in[2];
    const float* freq = (const float*)d_in[3];
    const float* w1   = (const float*)d_in[4];
    const float* b1   = (const float*)d_in[5];
    const float* w2   = (const float*)d_in[6];
    const float* b2   = (const float*)d_in[7];
    float* out = (float*)d_out;

    const int tot = 51 * 1024 + 34 * 512 + 17 * 512;
    prep_kernel<<<(tot + 255) / 256, 256>>>(w2, b2);

    cudaFuncSetAttribute(conv_mma_kernel,
                         cudaFuncAttributeMaxDynamicSharedMemorySize, SMEM_BYTES);
    const int nblocks = (E_TOT + EB - 1) / EB;   // 235
    conv_mma_kernel<<<nblocks, NTHR, SMEM_BYTES>>>(x, rps, dist, freq, w1, b1, out);
}